// round 13
// baseline (speedup 1.0000x reference)
#include <cuda_runtime.h>
#include <math_constants.h>
#include <cstddef>
#include <cstdint>

#define DIMC   512
#define HD     64
#define NHEADS 8
#define BATCH  4
#define SEQN   2048
#define SEQM   2048
#define ATT_SCALE 0.125f   // 64^-0.5 (power of two: exact fold into Q)

#define KS_LD 68   // attention K smem stride (floats)
#define VS_LD 72   // attention V smem stride (floats)
#define ANSTG 3    // attention cp.async pipeline depth

#define GA_LD 36   // gemm A smem stride
#define GB_LD 136  // gemm B smem stride

#define ATTN_SMEM_BYTES ((ANSTG * 64 * KS_LD + ANSTG * 64 * VS_LD) * 4)
#define MASK_WORDS (BATCH * SEQN * (SEQM / 32))

// ---------------- scratch (device globals: allocation-free) ----------------
__device__ float    g_Q   [BATCH * SEQN * DIMC];       // 16 MB (tf32-rounded)
__device__ float    g_KV  [BATCH * SEQM * 2 * DIMC];   // 32 MB (tf32-rounded)
__device__ float    g_O   [BATCH * SEQN * DIMC];       // 16 MB
__device__ uint32_t g_mask[MASK_WORDS];                // 2 MB bitpacked mask

// ---------------------------------------------------------------------------
// tf32 / async helpers
// ---------------------------------------------------------------------------
__device__ __forceinline__ float to_tf32(float x) {
    unsigned u;
    asm("cvt.rna.tf32.f32 %0, %1;" : "=r"(u) : "f"(x));
    return __uint_as_float(u);
}
__device__ __forceinline__ unsigned tf32_bits(float x) {
    unsigned u;
    asm("cvt.rna.tf32.f32 %0, %1;" : "=r"(u) : "f"(x));
    return u;
}
__device__ __forceinline__ void mma_tf32(float c[4], const unsigned a[4],
                                         unsigned b0, unsigned b1)
{
    asm volatile(
        "mma.sync.aligned.m16n8k8.row.col.f32.tf32.tf32.f32 "
        "{%0,%1,%2,%3},{%4,%5,%6,%7},{%8,%9},{%0,%1,%2,%3};"
        : "+f"(c[0]), "+f"(c[1]), "+f"(c[2]), "+f"(c[3])
        : "r"(a[0]), "r"(a[1]), "r"(a[2]), "r"(a[3]), "r"(b0), "r"(b1));
}
__device__ __forceinline__ void cp_async16(uint32_t smem_addr, const void* gptr) {
    asm volatile("cp.async.cg.shared.global [%0], [%1], 16;"
                 :: "r"(smem_addr), "l"(gptr));
}
__device__ __forceinline__ void cp_commit() {
    asm volatile("cp.async.commit_group;");
}
template <int N>
__device__ __forceinline__ void cp_wait() {
    asm volatile("cp.async.wait_group %0;" :: "n"(N));
}
__device__ __forceinline__ uint32_t smem_u32(const void* p) {
    return (uint32_t)__cvta_generic_to_shared(p);
}

// ---------------------------------------------------------------------------
// Mask bit-pack: 32 int32 -> 1 uint32 via ballot.
// ---------------------------------------------------------------------------
__global__ __launch_bounds__(256) void pack_mask(const int* __restrict__ mask,
                                                 uint32_t* __restrict__ bm, int n)
{
    int idx = blockIdx.x * blockDim.x + threadIdx.x;
    if (idx < n) {
        unsigned bal = __ballot_sync(0xffffffffu, mask[idx] != 0);
        if ((threadIdx.x & 31) == 0) bm[idx >> 5] = bal;
    }
}

// ---------------------------------------------------------------------------
// R10 GEMM body (reg prefetch + cvt-at-store; measured 40.3us/launch),
// shared by the fused Q+KV kernel and the O-projection kernel.
// Computes the 128x128 tile (bm0,bn0) of C = A@B. One CTA, 256 threads.
// ---------------------------------------------------------------------------
template <bool RND>
__device__ __forceinline__ void gemm_tile(const float* __restrict__ A,
                                          const float* __restrict__ B,
                                          float* __restrict__ C,
                                          int N, int K, int bm0, int bn0)
{
    __shared__ __align__(16) float As[128 * GA_LD];
    __shared__ __align__(16) float Bs[32 * GB_LD];

    const int tid  = threadIdx.x;
    const int warp = tid >> 5;
    const int lane = tid & 31;
    const int q4   = lane >> 2;
    const int l4   = lane & 3;
    const int wm   = (warp >> 1) * 32;
    const int wn   = (warp & 1) * 64;

    const int a_row  = tid >> 3;
    const int a_col4 = (tid & 7) * 4;
    const int b_row  = tid >> 5;
    const int b_col4 = (tid & 31) * 4;

    const float* Abase = A + (size_t)(bm0 + a_row) * K + a_col4;
    const float* Bbase = B + (size_t)b_row * N + bn0 + b_col4;

    float acc[2][8][4];
#pragma unroll
    for (int mf = 0; mf < 2; mf++)
#pragma unroll
        for (int nf = 0; nf < 8; nf++)
#pragma unroll
            for (int c = 0; c < 4; c++) acc[mf][nf][c] = 0.0f;

    const int NT = K / 32;
    float4 ar[4], br[4];

#pragma unroll
    for (int e = 0; e < 4; e++) {
        ar[e] = *(const float4*)(Abase + (size_t)(e * 32) * K);
        br[e] = *(const float4*)(Bbase + (size_t)(e * 8) * N);
    }

    for (int kt = 0; kt < NT; kt++) {
#pragma unroll
        for (int e = 0; e < 4; e++) {
            float* ad = &As[(a_row + e * 32) * GA_LD + a_col4];
            ad[0] = to_tf32(ar[e].x); ad[1] = to_tf32(ar[e].y);
            ad[2] = to_tf32(ar[e].z); ad[3] = to_tf32(ar[e].w);
            float* bd = &Bs[(b_row + e * 8) * GB_LD + b_col4];
            bd[0] = to_tf32(br[e].x); bd[1] = to_tf32(br[e].y);
            bd[2] = to_tf32(br[e].z); bd[3] = to_tf32(br[e].w);
        }
        __syncthreads();

        if (kt + 1 < NT) {
            const float* An = Abase + (kt + 1) * 32;
            const float* Bn = Bbase + (size_t)((kt + 1) * 32) * N;
#pragma unroll
            for (int e = 0; e < 4; e++) {
                ar[e] = *(const float4*)(An + (size_t)(e * 32) * K);
                br[e] = *(const float4*)(Bn + (size_t)(e * 8) * N);
            }
        }

#pragma unroll
        for (int kk = 0; kk < 4; kk++) {
            unsigned a[2][4];
#pragma unroll
            for (int mf = 0; mf < 2; mf++) {
                int r = wm + mf * 16 + q4;
                int c0 = kk * 8 + l4;
                a[mf][0] = __float_as_uint(As[(r    ) * GA_LD + c0    ]);
                a[mf][1] = __float_as_uint(As[(r + 8) * GA_LD + c0    ]);
                a[mf][2] = __float_as_uint(As[(r    ) * GA_LD + c0 + 4]);
                a[mf][3] = __float_as_uint(As[(r + 8) * GA_LD + c0 + 4]);
            }
#pragma unroll
            for (int nf = 0; nf < 8; nf++) {
                int n = wn + nf * 8 + q4;
                unsigned b0 = __float_as_uint(Bs[(kk * 8 + l4    ) * GB_LD + n]);
                unsigned b1 = __float_as_uint(Bs[(kk * 8 + l4 + 4) * GB_LD + n]);
                mma_tf32(acc[0][nf], a[0], b0, b1);
                mma_tf32(acc[1][nf], a[1], b0, b1);
            }
        }
        __syncthreads();
    }

#pragma unroll
    for (int mf = 0; mf < 2; mf++) {
        int r = bm0 + wm + mf * 16 + q4;
#pragma unroll
        for (int nf = 0; nf < 8; nf++) {
            int cidx = bn0 + wn + nf * 8 + 2 * l4;
            float v0 = acc[mf][nf][0], v1 = acc[mf][nf][1];
            float v2 = acc[mf][nf][2], v3 = acc[mf][nf][3];
            if (RND) {
                v0 = to_tf32(v0); v1 = to_tf32(v1);
                v2 = to_tf32(v2); v3 = to_tf32(v3);
            }
            float2 lo = {v0, v1};
            float2 hi = {v2, v3};
            *(float2*)(C + (size_t)r * N + cidx)       = lo;
            *(float2*)(C + (size_t)(r + 8) * N + cidx) = hi;
        }
    }
}

// Fused Q-proj + KV-proj: grid.x = 4 (Q cols) + 8 (KV cols) = 12, grid.y = 64.
__global__ __launch_bounds__(256) void proj_qkv(const float* __restrict__ x,
                                                const float* __restrict__ ctx,
                                                const float* __restrict__ Wq,
                                                const float* __restrict__ Wkv,
                                                float* __restrict__ Q,
                                                float* __restrict__ KV)
{
    const int bx  = blockIdx.x;
    const int bm0 = blockIdx.y * 128;
    if (bx < 4) {
        gemm_tile<true>(x, Wq, Q, DIMC, DIMC, bm0, bx * 128);
    } else {
        gemm_tile<true>(ctx, Wkv, KV, 2 * DIMC, DIMC, bm0, (bx - 4) * 128);
    }
}

// O projection (exact fp32 output).
__global__ __launch_bounds__(256) void proj_o(const float* __restrict__ Oin,
                                              const float* __restrict__ Wo,
                                              float* __restrict__ out)
{
    gemm_tile<false>(Oin, Wo, out, DIMC, DIMC, blockIdx.y * 128, blockIdx.x * 128);
}

// ---------------------------------------------------------------------------
// Tensor-core flash attention v6: 3-stage cp.async K/V pipeline -> ONE
// __syncthreads per KV tile (slot (t-1)%3 is free at the top-of-loop barrier).
// 256 threads (8 warps), 16 queries/warp, 128 queries/CTA; pre-rounded tf32
// inputs; ATT_SCALE folded into Q; bitpacked mask with all-ones fast path.
// Grid: (SEQN/128, NHEADS, BATCH).
// ---------------------------------------------------------------------------
__global__ __launch_bounds__(256, 2) void attn_tc(const float* __restrict__ Qm,
                                                  const float* __restrict__ KVm,
                                                  const uint32_t* __restrict__ bmask,
                                                  float* __restrict__ Om)
{
    extern __shared__ __align__(16) float smem[];
    float* Ks = smem;                             // ANSTG x 64 x KS_LD
    float* Vs = smem + ANSTG * 64 * KS_LD;        // ANSTG x 64 x VS_LD

    const int tid  = threadIdx.x;
    const int warp = tid >> 5;
    const int lane = tid & 31;
    const int q4   = lane >> 2;
    const int l4   = lane & 3;
    const int n0   = blockIdx.x * 128;
    const int h    = blockIdx.y;
    const int b    = blockIdx.z;
    const int r0   = warp * 16;

    const float* Qbase  = Qm  + ((size_t)b * SEQN) * DIMC       + h * HD;
    const float* KVbase = KVm + ((size_t)b * SEQM) * (2 * DIMC) + h * HD;

    // ---- stage Q (pre-rounded tf32, 128x64) into the Ks region ----
#pragma unroll
    for (int e = 0; e < 8; e++) {
        int i4 = tid + e * 256;
        int i  = i4 >> 4;
        int c4 = (i4 & 15) << 2;
        float4 v = *(const float4*)(Qbase + (size_t)(n0 + i) * DIMC + c4);
        *(float4*)&Ks[i * KS_LD + c4] = v;
    }
    __syncthreads();

    // ---- build Q A-fragments with ATT_SCALE folded in (exact x2^-3) ----
    unsigned qa[8][4];
#pragma unroll
    for (int kt = 0; kt < 8; kt++) {
        int r = r0 + q4;
        qa[kt][0] = __float_as_uint(ATT_SCALE * Ks[(r    ) * KS_LD + kt * 8 + l4    ]);
        qa[kt][1] = __float_as_uint(ATT_SCALE * Ks[(r + 8) * KS_LD + kt * 8 + l4    ]);
        qa[kt][2] = __float_as_uint(ATT_SCALE * Ks[(r    ) * KS_LD + kt * 8 + l4 + 4]);
        qa[kt][3] = __float_as_uint(ATT_SCALE * Ks[(r + 8) * KS_LD + kt * 8 + l4 + 4]);
    }
    __syncthreads();   // Q reads done; Ks region reusable for K tiles

    const int T = SEQM / 64;

    // issue KV tile t into pipeline slot t % ANSTG (empty group if t >= T)
    auto issue_tile = [&](int t) {
        if (t < T) {
            int s = t % ANSTG;
            float* kb = Ks + s * 64 * KS_LD;
            float* vb = Vs + s * 64 * VS_LD;
            const float* base = KVbase + (size_t)(t * 64) * (2 * DIMC);
#pragma unroll
            for (int e = 0; e < 4; e++) {
                int i4 = tid + e * 256;
                int j  = i4 >> 4;
                int d4 = (i4 & 15) << 2;
                const float* row = base + (size_t)j * (2 * DIMC) + d4;
                cp_async16(smem_u32(&kb[j * KS_LD + d4]), row);
                cp_async16(smem_u32(&vb[j * VS_LD + d4]), row + DIMC);
            }
        }
        cp_commit();
    };

    issue_tile(0);
    issue_tile(1);

    float oc[8][4];
#pragma unroll
    for (int nt = 0; nt < 8; nt++)
#pragma unroll
        for (int c = 0; c < 4; c++) oc[nt][c] = 0.0f;
    float mrun_lo = -CUDART_INF_F, mrun_hi = -CUDART_INF_F;
    float lsum_lo = 0.0f, lsum_hi = 0.0f;

    const int i0 = n0 + r0 + q4;
    const int i1 = i0 + 8;
    const uint32_t* mp0 = bmask + ((size_t)(b * SEQN + i0) * (SEQM / 32));
    const uint32_t* mp1 = bmask + ((size_t)(b * SEQN + i1) * (SEQM / 32));

    for (int t = 0; t < T; t++) {
        cp_wait<1>();          // group(t) complete (group(t+1) may be in flight)
        __syncthreads();       // visibility + slot (t-1)%3 free in all warps
        issue_tile(t + 2);     // into slot (t+2)%3 == (t-1)%3

        const float* kb = Ks + (t % ANSTG) * 64 * KS_LD;
        const float* vb = Vs + (t % ANSTG) * 64 * VS_LD;

        // ---- prefetch bitmask words (overlap QK MMAs) ----
        uint2 mw0 = *(const uint2*)(mp0 + t * 2);
        uint2 mw1 = *(const uint2*)(mp1 + t * 2);

        // ---- S = (Q*scale) K^T ----
        float sc[8][4];
#pragma unroll
        for (int nt = 0; nt < 8; nt++)
#pragma unroll
            for (int c = 0; c < 4; c++) sc[nt][c] = 0.0f;
#pragma unroll
        for (int kt = 0; kt < 8; kt++) {
#pragma unroll
            for (int nt = 0; nt < 8; nt++) {
                int jrow = nt * 8 + q4;
                unsigned b0 = __float_as_uint(kb[jrow * KS_LD + kt * 8 + l4    ]);
                unsigned b1 = __float_as_uint(kb[jrow * KS_LD + kt * 8 + l4 + 4]);
                mma_tf32(sc[nt], qa[kt], b0, b1);
            }
        }

        // ---- mask (all-ones fast path; bit test otherwise) ----
        if ((mw0.x & mw0.y & mw1.x & mw1.y) != 0xffffffffu) {
#pragma unroll
            for (int nt = 0; nt < 8; nt++) {
                uint32_t wlo = (nt < 4) ? mw0.x : mw0.y;
                uint32_t whi = (nt < 4) ? mw1.x : mw1.y;
                int bit = (nt * 8 + 2 * l4) & 31;
                if (!((wlo >> bit) & 1u))       sc[nt][0] = -CUDART_INF_F;
                if (!((wlo >> (bit + 1)) & 1u)) sc[nt][1] = -CUDART_INF_F;
                if (!((whi >> bit) & 1u))       sc[nt][2] = -CUDART_INF_F;
                if (!((whi >> (bit + 1)) & 1u)) sc[nt][3] = -CUDART_INF_F;
            }
        }

        // ---- online softmax (exp(-inf)=0 handles masked entries) ----
        float tml = -CUDART_INF_F, tmh = -CUDART_INF_F;
#pragma unroll
        for (int nt = 0; nt < 8; nt++) {
            tml = fmaxf(tml, fmaxf(sc[nt][0], sc[nt][1]));
            tmh = fmaxf(tmh, fmaxf(sc[nt][2], sc[nt][3]));
        }
        tml = fmaxf(tml, __shfl_xor_sync(0xffffffffu, tml, 1));
        tml = fmaxf(tml, __shfl_xor_sync(0xffffffffu, tml, 2));
        tmh = fmaxf(tmh, __shfl_xor_sync(0xffffffffu, tmh, 1));
        tmh = fmaxf(tmh, __shfl_xor_sync(0xffffffffu, tmh, 2));

        float mnew_lo = fmaxf(mrun_lo, tml);
        float mnew_hi = fmaxf(mrun_hi, tmh);

        float ssl = 0.0f, ssh = 0.0f;
#pragma unroll
        for (int nt = 0; nt < 8; nt++) {
            float p0 = __expf(sc[nt][0] - mnew_lo);
            float p1 = __expf(sc[nt][1] - mnew_lo);
            float p2 = __expf(sc[nt][2] - mnew_hi);
            float p3 = __expf(sc[nt][3] - mnew_hi);
            sc[nt][0] = p0; sc[nt][1] = p1; sc[nt][2] = p2; sc[nt][3] = p3;
            ssl += p0 + p1;
            ssh += p2 + p3;
        }
        ssl += __shfl_xor_sync(0xffffffffu, ssl, 1);
        ssl += __shfl_xor_sync(0xffffffffu, ssl, 2);
        ssh += __shfl_xor_sync(0xffffffffu, ssh, 1);
        ssh += __shfl_xor_sync(0xffffffffu, ssh, 2);

        float alpha_lo = __expf(mrun_lo - mnew_lo);   // first tile: exp(-inf)=0
        float alpha_hi = __expf(mrun_hi - mnew_hi);
        lsum_lo = lsum_lo * alpha_lo + ssl;
        lsum_hi = lsum_hi * alpha_hi + ssh;
        mrun_lo = mnew_lo;
        mrun_hi = mnew_hi;
#pragma unroll
        for (int nt = 0; nt < 8; nt++) {
            oc[nt][0] *= alpha_lo; oc[nt][1] *= alpha_lo;
            oc[nt][2] *= alpha_hi; oc[nt][3] *= alpha_hi;
        }

        // ---- O += P @ V ----
        const int base2 = lane & ~3;
        const int src  = base2 | (l4 >> 1);
        const int src2 = src + 2;
        const bool odd = lane & 1;
#pragma unroll
        for (int kt = 0; kt < 8; kt++) {
            float c0 = sc[kt][0], c1 = sc[kt][1], c2 = sc[kt][2], c3 = sc[kt][3];
            float t00 = __shfl_sync(0xffffffffu, c0, src);
            float t01 = __shfl_sync(0xffffffffu, c1, src);
            float t10 = __shfl_sync(0xffffffffu, c2, src);
            float t11 = __shfl_sync(0xffffffffu, c3, src);
            float t20 = __shfl_sync(0xffffffffu, c0, src2);
            float t21 = __shfl_sync(0xffffffffu, c1, src2);
            float t30 = __shfl_sync(0xffffffffu, c2, src2);
            float t31 = __shfl_sync(0xffffffffu, c3, src2);
            unsigned pa[4];
            pa[0] = tf32_bits(odd ? t01 : t00);
            pa[1] = tf32_bits(odd ? t11 : t10);
            pa[2] = tf32_bits(odd ? t21 : t20);
            pa[3] = tf32_bits(odd ? t31 : t30);
#pragma unroll
            for (int nt = 0; nt < 8; nt++) {
                int vrow = kt * 8 + l4;
                unsigned b0 = __float_as_uint(vb[(vrow    ) * VS_LD + nt * 8 + q4]);
                unsigned b1 = __float_as_uint(vb[(vrow + 4) * VS_LD + nt * 8 + q4]);
                mma_tf32(oc[nt], pa, b0, b1);
            }
        }
    }

    // ---- normalize + write O ----
    float inv_lo = 1.0f / lsum_lo;
    float inv_hi = 1.0f / lsum_hi;
    float* orow0 = Om + (size_t)(b * SEQN + i0) * DIMC + h * HD;
    float* orow1 = Om + (size_t)(b * SEQN + i1) * DIMC + h * HD;
#pragma unroll
    for (int nt = 0; nt < 8; nt++) {
        int d0 = nt * 8 + 2 * l4;
        float2 lo = {oc[nt][0] * inv_lo, oc[nt][1] * inv_lo};
        float2 hi = {oc[nt][2] * inv_hi, oc[nt][3] * inv_hi};
        *(float2*)(orow0 + d0) = lo;
        *(float2*)(orow1 + d0) = hi;
    }
}

// ---------------------------------------------------------------------------
extern "C" void kernel_launch(void* const* d_in, const int* in_sizes, int n_in,
                              void* d_out, int out_size)
{
    const float* x    = (const float*)d_in[0];
    const float* ctx  = (const float*)d_in[1];
    const int*   mask = (const int*)d_in[2];
    const float* Wq   = (const float*)d_in[3];
    const float* Wkv  = (const float*)d_in[4];
    const float* Wo   = (const float*)d_in[5];
    float*       out  = (float*)d_out;

    float *gQ, *gKV, *gO;
    uint32_t* gM;
    cudaGetSymbolAddress((void**)&gQ,  g_Q);
    cudaGetSymbolAddress((void**)&gKV, g_KV);
    cudaGetSymbolAddress((void**)&gO,  g_O);
    cudaGetSymbolAddress((void**)&gM,  g_mask);

    cudaFuncSetAttribute(attn_tc, cudaFuncAttributeMaxDynamicSharedMemorySize,
                         ATTN_SMEM_BYTES);

    const int Mrows = BATCH * SEQN;   // 8192
    const int mask_n = BATCH * SEQN * SEQM;

    pack_mask<<<mask_n / 256, 256>>>(mask, gM, mask_n);
    // fused Q + KV projections (one launch, 768 CTAs)
    proj_qkv<<<dim3(12, Mrows / 128), 256>>>(x, ctx, Wq, Wkv, gQ, gKV);
    attn_tc<<<dim3(SEQN / 128, NHEADS, BATCH), 256, ATTN_SMEM_BYTES>>>(gQ, gKV, gM, gO);
    proj_o<<<dim3(DIMC / 128, Mrows / 128), 256>>>(gO, Wo, out);
}